// round 5
// baseline (speedup 1.0000x reference)
#include <cuda_runtime.h>

#define N   128
#define N2  (128 * 128)
#define N3  (128 * 128 * 128)

// Scratch (no allocations allowed)
__device__ float g_warped[N3];
__device__ float g_u[3 * N3];

// Gaussian weights sigma=1, radius=3, normalized
__constant__ float GW[4] = {0.39905027f, 0.24203622f, 0.05400558f, 0.00443305f};

__global__ void zero_kernel(float4* __restrict__ vf) {
    int i = blockIdx.x * blockDim.x + threadIdx.x;
    if (i < 3 * N3 / 4) vf[i] = make_float4(0.f, 0.f, 0.f, 0.f);
}

// ---------------------------------------------------------------------------
// Trilinear warp: each thread handles 4 consecutive-w voxels.
// map_coordinates(order=1, mode='nearest') == clamp coordinate to [0, N-1].
// ---------------------------------------------------------------------------
__device__ __forceinline__ float trilerp(const float* __restrict__ m,
                                         float cd, float ch, float cw) {
    cd = fminf(fmaxf(cd, 0.0f), 127.0f);
    ch = fminf(fmaxf(ch, 0.0f), 127.0f);
    cw = fminf(fmaxf(cw, 0.0f), 127.0f);
    int d0 = (int)cd, h0 = (int)ch, w0 = (int)cw;
    float fd = cd - (float)d0, fh = ch - (float)h0, fw = cw - (float)w0;
    int d1 = min(d0 + 1, 127), h1 = min(h0 + 1, 127), w1 = min(w0 + 1, 127);

    const float* p0 = m + (d0 << 14);
    const float* p1 = m + (d1 << 14);
    int r0 = (h0 << 7), r1 = (h1 << 7);

    float v000 = p0[r0 + w0], v001 = p0[r0 + w1];
    float v010 = p0[r1 + w0], v011 = p0[r1 + w1];
    float v100 = p1[r0 + w0], v101 = p1[r0 + w1];
    float v110 = p1[r1 + w0], v111 = p1[r1 + w1];

    float c00 = v000 + fw * (v001 - v000);
    float c01 = v010 + fw * (v011 - v010);
    float c10 = v100 + fw * (v101 - v100);
    float c11 = v110 + fw * (v111 - v110);
    float c0 = c00 + fh * (c01 - c00);
    float c1 = c10 + fh * (c11 - c10);
    return c0 + fd * (c1 - c0);
}

__global__ void warp_kernel(const float* __restrict__ moving,
                            const float4* __restrict__ vf4,
                            float4* __restrict__ warped4) {
    int i4 = blockIdx.x * blockDim.x + threadIdx.x;   // over N3/4
    if (i4 >= N3 / 4) return;
    int i = i4 * 4;
    int w = i & 127;
    int h = (i >> 7) & 127;
    int d = i >> 14;

    float4 vd = vf4[i4];
    float4 vh = vf4[i4 + N3 / 4];
    float4 vw = vf4[i4 + 2 * N3 / 4];

    float4 out;
    out.x = trilerp(moving, (float)d + vd.x, (float)h + vh.x, (float)(w + 0) + vw.x);
    out.y = trilerp(moving, (float)d + vd.y, (float)h + vh.y, (float)(w + 1) + vw.y);
    out.z = trilerp(moving, (float)d + vd.z, (float)h + vh.z, (float)(w + 2) + vw.z);
    out.w = trilerp(moving, (float)d + vd.w, (float)h + vh.w, (float)(w + 3) + vw.w);
    warped4[i4] = out;
}

// ---------------------------------------------------------------------------
// Demon forces (dual) + u = vf + f, then W-axis 7-tap smooth via warp shuffle.
// Lane l holds w = [4l, 4l+3]; a warp spans a full 128-wide row.
// ---------------------------------------------------------------------------
__device__ __forceinline__ float4 grad_s(const float4* __restrict__ a4,
                                         int i4, int c, int s4) {
    float4 p, m;
    if (c == 0) {
        p = a4[i4 + s4]; m = a4[i4];
        return make_float4(p.x - m.x, p.y - m.y, p.z - m.z, p.w - m.w);
    }
    if (c == 127) {
        p = a4[i4]; m = a4[i4 - s4];
        return make_float4(p.x - m.x, p.y - m.y, p.z - m.z, p.w - m.w);
    }
    p = a4[i4 + s4]; m = a4[i4 - s4];
    return make_float4(0.5f * (p.x - m.x), 0.5f * (p.y - m.y),
                       0.5f * (p.z - m.z), 0.5f * (p.w - m.w));
}

__device__ __forceinline__ float4 grad_w_shfl(float4 c, int lane) {
    float lw = __shfl_up_sync(0xFFFFFFFFu, c.w, 1);    // value at w0-1
    float rx = __shfl_down_sync(0xFFFFFFFFu, c.x, 1);  // value at w0+4
    float4 g;
    g.x = (lane == 0)  ? (c.y - c.x) : 0.5f * (c.y - lw);
    g.y = 0.5f * (c.z - c.x);
    g.z = 0.5f * (c.w - c.y);
    g.w = (lane == 31) ? (c.w - c.z) : 0.5f * (rx - c.z);
    return g;
}

__device__ __forceinline__ float4 wsmooth_shfl(float4 u, int lane) {
    float ly = __shfl_up_sync(0xFFFFFFFFu, u.y, 1);
    float lz = __shfl_up_sync(0xFFFFFFFFu, u.z, 1);
    float lw = __shfl_up_sync(0xFFFFFFFFu, u.w, 1);
    float rx = __shfl_down_sync(0xFFFFFFFFu, u.x, 1);
    float ry = __shfl_down_sync(0xFFFFFFFFu, u.y, 1);
    float rz = __shfl_down_sync(0xFFFFFFFFu, u.z, 1);
    if (lane == 0)  { ly = 0.f; lz = 0.f; lw = 0.f; }
    if (lane == 31) { rx = 0.f; ry = 0.f; rz = 0.f; }
    float a[10] = {ly, lz, lw, u.x, u.y, u.z, u.w, rx, ry, rz};
    float4 o;
#pragma unroll
    for (int j = 0; j < 4; j++) {
        float acc = GW[0] * a[3 + j];
#pragma unroll
        for (int t = 1; t <= 3; t++)
            acc += GW[t] * (a[3 + j - t] + a[3 + j + t]);
        ((float*)&o)[j] = acc;
    }
    return o;
}

__global__ void force_w_kernel(const float4* __restrict__ warped4,
                               const float4* __restrict__ fixed4,
                               const float4* __restrict__ vf4,
                               float4* __restrict__ u4) {
    int i4 = blockIdx.x * blockDim.x + threadIdx.x;   // over N3/4
    if (i4 >= N3 / 4) return;
    int i = i4 * 4;
    int h = (i >> 7) & 127;
    int d = i >> 14;
    int lane = threadIdx.x & 31;   // == w4 index within the row

    float4 wc = warped4[i4];
    float4 fc = fixed4[i4];

    float4 gdw = grad_s(warped4, i4, d, N2 / 4);
    float4 gdf = grad_s(fixed4,  i4, d, N2 / 4);
    float4 ghw = grad_s(warped4, i4, h, N / 4);
    float4 ghf = grad_s(fixed4,  i4, h, N / 4);
    float4 gww = grad_w_shfl(wc, lane);
    float4 gwf = grad_w_shfl(fc, lane);

    float4 v0 = vf4[i4];
    float4 v1 = vf4[i4 + N3 / 4];
    float4 v2 = vf4[i4 + 2 * N3 / 4];

    float4 u0, u1, u2;
#pragma unroll
    for (int j = 0; j < 4; j++) {
        float diff = ((const float*)&wc)[j] - ((const float*)&fc)[j];
        float g0 = 0.5f * (((const float*)&gdw)[j] + ((const float*)&gdf)[j]);
        float g1 = 0.5f * (((const float*)&ghw)[j] + ((const float*)&ghf)[j]);
        float g2 = 0.5f * (((const float*)&gww)[j] + ((const float*)&gwf)[j]);
        float denom = g0 * g0 + g1 * g1 + g2 * g2 + diff * diff;
        float s = (denom > 1e-6f) ? (diff / denom) : 0.0f;
        ((float*)&u0)[j] = ((const float*)&v0)[j] + s * g0;
        ((float*)&u1)[j] = ((const float*)&v1)[j] + s * g1;
        ((float*)&u2)[j] = ((const float*)&v2)[j] + s * g2;
    }

    // Fused W-axis smoothing (separable passes commute)
    u4[i4]              = wsmooth_shfl(u0, lane);
    u4[i4 + N3 / 4]     = wsmooth_shfl(u1, lane);
    u4[i4 + 2 * N3 / 4] = wsmooth_shfl(u2, lane);
}

// ---------------------------------------------------------------------------
// Fused D+H 7-tap Gaussian (zero-padded), one shared-memory 2D tile.
// Tile: TD x TH outputs, WC float4s wide in w. Halo 3 on both tile axes.
// Stage 1: D-smooth (TD+6->TD rows kept in h-halo form) into smem.
// Stage 2: H-smooth from smem, store to vf.
// ---------------------------------------------------------------------------
#define TD 16
#define TH 32
#define WC 2
#define ROWW ((TH + 6) * WC)          // 76 float4 per d-row in tile

__global__ void smooth_dh_kernel(const float4* __restrict__ in4,
                                 float4* __restrict__ out4) {
    __shared__ float4 sIn[(TD + 6) * ROWW];   // 22*76 = 1672 f4 = 26.8 KB
    __shared__ float4 sMid[TD * ROWW];        // 16*76 = 1216 f4 = 19.5 KB

    int b = blockIdx.x;
    int wc = b & 15;                  // 16 w-chunks of WC float4
    int hb = (b >> 4) & 3;            // 4 h tiles of TH
    int db = (b >> 6) & 7;            // 8 d tiles of TD
    int ch = b >> 9;                  // 3 channels
    int d0 = db * TD, h0 = hb * TH, wbase = wc * WC;

    const float4* src = in4 + (size_t)ch * (N3 / 4);
    float4*       dst = out4 + (size_t)ch * (N3 / 4);

    // Load input tile with zero padding outside the volume
    for (int t = threadIdx.x; t < (TD + 6) * ROWW; t += blockDim.x) {
        int iw = t % WC;
        int ih = (t / WC) % (TH + 6);
        int id = t / ROWW;
        int d = d0 + id - 3, h = h0 + ih - 3;
        float4 v = make_float4(0.f, 0.f, 0.f, 0.f);
        if (d >= 0 && d < 128 && h >= 0 && h < 128)
            v = src[d * (N2 / 4) + h * (N / 4) + wbase + iw];
        sIn[t] = v;
    }
    __syncthreads();

    // Stage 1: D-axis smooth for all (TH+6) h-rows
    for (int t = threadIdx.x; t < TD * ROWW; t += blockDim.x) {
        int col = t % ROWW;
        int id = t / ROWW;
        const float4* p = sIn + col;
        float4 c = p[(id + 3) * ROWW];
        float4 acc = make_float4(GW[0] * c.x, GW[0] * c.y, GW[0] * c.z, GW[0] * c.w);
#pragma unroll
        for (int s = 1; s <= 3; s++) {
            float4 a = p[(id + 3 - s) * ROWW];
            float4 bb = p[(id + 3 + s) * ROWW];
            acc.x += GW[s] * (a.x + bb.x);
            acc.y += GW[s] * (a.y + bb.y);
            acc.z += GW[s] * (a.z + bb.z);
            acc.w += GW[s] * (a.w + bb.w);
        }
        sMid[t] = acc;
    }
    __syncthreads();

    // Stage 2: H-axis smooth, write out
    for (int t = threadIdx.x; t < TD * TH * WC; t += blockDim.x) {
        int iw = t % WC;
        int ih = (t / WC) % TH;
        int id = t / (TH * WC);
        const float4* p = sMid + id * ROWW + iw;
        float4 c = p[(ih + 3) * WC];
        float4 acc = make_float4(GW[0] * c.x, GW[0] * c.y, GW[0] * c.z, GW[0] * c.w);
#pragma unroll
        for (int s = 1; s <= 3; s++) {
            float4 a = p[(ih + 3 - s) * WC];
            float4 bb = p[(ih + 3 + s) * WC];
            acc.x += GW[s] * (a.x + bb.x);
            acc.y += GW[s] * (a.y + bb.y);
            acc.z += GW[s] * (a.z + bb.z);
            acc.w += GW[s] * (a.w + bb.w);
        }
        dst[(d0 + id) * (N2 / 4) + (h0 + ih) * (N / 4) + wbase + iw] = acc;
    }
}

extern "C" void kernel_launch(void* const* d_in, const int* in_sizes, int n_in,
                              void* d_out, int out_size) {
    const float* moving = (const float*)d_in[0];
    const float4* fixed4 = (const float4*)d_in[1];
    float4* vf4 = (float4*)d_out;

    float *warped_p, *u_p;
    cudaGetSymbolAddress((void**)&warped_p, g_warped);
    cudaGetSymbolAddress((void**)&u_p, g_u);
    float4* warped4 = (float4*)warped_p;
    float4* u4 = (float4*)u_p;

    const int T = 256;
    const int B1 = (N3 / 4) / T;            // 2048
    const int B3 = (3 * N3 / 4) / T;        // 6144
    const int BDH = 3 * 8 * 4 * 16;         // 1536 tiles

    zero_kernel<<<B3, T>>>(vf4);

    for (int it = 0; it < 20; it++) {
        warp_kernel<<<B1, T>>>(moving, vf4, warped4);
        force_w_kernel<<<B1, T>>>(warped4, fixed4, vf4, u4);   // force + W smooth
        smooth_dh_kernel<<<BDH, T>>>(u4, vf4);                 // fused D + H smooth
    }
}

// round 11
// speedup vs baseline: 1.4772x; 1.4772x over previous
#include <cuda_runtime.h>
#include <cuda_fp16.h>

#define N   128
#define N2  (128 * 128)
#define N3  (128 * 128 * 128)

// Scratch (no allocations allowed)
__device__ float  g_warped[N3];         // fp32: feeds gradients/denominator
__device__ __half g_vfh[3 * N3];        // fp16 internal velocity field
__device__ __half g_uh[3 * N3];         // fp16 u = vf + f (W-smoothed)
__device__ __half g_th[3 * N3];         // fp16 D-smoothed intermediate

// Gaussian weights sigma=1, radius=3, normalized
__constant__ float GW[4] = {0.39905027f, 0.24203622f, 0.05400558f, 0.00443305f};

// ---- fp16x4 <-> float4 helpers (uint2 = 4 halves = 4 voxels) ----
__device__ __forceinline__ float4 ld_h4(const uint2* __restrict__ p, int idx) {
    uint2 v = p[idx];
    __half2 a = __halves2half2(__ushort_as_half((unsigned short)(v.x & 0xFFFFu)),
                               __ushort_as_half((unsigned short)(v.x >> 16)));
    __half2 b = __halves2half2(__ushort_as_half((unsigned short)(v.y & 0xFFFFu)),
                               __ushort_as_half((unsigned short)(v.y >> 16)));
    float2 fa = __half22float2(a), fb = __half22float2(b);
    return make_float4(fa.x, fa.y, fb.x, fb.y);
}
__device__ __forceinline__ void st_h4(uint2* __restrict__ p, int idx, float4 v) {
    __half2 a = __floats2half2_rn(v.x, v.y);
    __half2 b = __floats2half2_rn(v.z, v.w);
    uint2 u;
    u.x = (unsigned)__half_as_ushort(__low2half(a)) |
          ((unsigned)__half_as_ushort(__high2half(a)) << 16);
    u.y = (unsigned)__half_as_ushort(__low2half(b)) |
          ((unsigned)__half_as_ushort(__high2half(b)) << 16);
    p[idx] = u;
}

__global__ void zero_h_kernel(uint4* __restrict__ vfh) {
    int i = blockIdx.x * blockDim.x + threadIdx.x;
    if (i < 3 * N3 / 8) vfh[i] = make_uint4(0u, 0u, 0u, 0u);
}

// ---------------------------------------------------------------------------
// Trilinear warp (4 consecutive-w voxels per thread); vf read as fp16.
// map_coordinates(order=1, mode='nearest') == clamp coordinate to [0, N-1].
// ---------------------------------------------------------------------------
__device__ __forceinline__ float trilerp(const float* __restrict__ m,
                                         float cd, float ch, float cw) {
    cd = fminf(fmaxf(cd, 0.0f), 127.0f);
    ch = fminf(fmaxf(ch, 0.0f), 127.0f);
    cw = fminf(fmaxf(cw, 0.0f), 127.0f);
    int d0 = (int)cd, h0 = (int)ch, w0 = (int)cw;
    float fd = cd - (float)d0, fh = ch - (float)h0, fw = cw - (float)w0;
    int d1 = min(d0 + 1, 127), h1 = min(h0 + 1, 127), w1 = min(w0 + 1, 127);

    const float* p0 = m + (d0 << 14);
    const float* p1 = m + (d1 << 14);
    int r0 = (h0 << 7), r1 = (h1 << 7);

    float v000 = p0[r0 + w0], v001 = p0[r0 + w1];
    float v010 = p0[r1 + w0], v011 = p0[r1 + w1];
    float v100 = p1[r0 + w0], v101 = p1[r0 + w1];
    float v110 = p1[r1 + w0], v111 = p1[r1 + w1];

    float c00 = v000 + fw * (v001 - v000);
    float c01 = v010 + fw * (v011 - v010);
    float c10 = v100 + fw * (v101 - v100);
    float c11 = v110 + fw * (v111 - v110);
    float c0 = c00 + fh * (c01 - c00);
    float c1 = c10 + fh * (c11 - c10);
    return c0 + fd * (c1 - c0);
}

__global__ void warp_kernel(const float* __restrict__ moving,
                            const uint2* __restrict__ vfh,
                            float4* __restrict__ warped4) {
    int i4 = blockIdx.x * blockDim.x + threadIdx.x;   // over N3/4
    if (i4 >= N3 / 4) return;
    int i = i4 * 4;
    int w = i & 127;
    int h = (i >> 7) & 127;
    int d = i >> 14;

    float4 vd = ld_h4(vfh, i4);
    float4 vh = ld_h4(vfh, i4 + N3 / 4);
    float4 vw = ld_h4(vfh, i4 + 2 * N3 / 4);

    float4 out;
    out.x = trilerp(moving, (float)d + vd.x, (float)h + vh.x, (float)(w + 0) + vw.x);
    out.y = trilerp(moving, (float)d + vd.y, (float)h + vh.y, (float)(w + 1) + vw.y);
    out.z = trilerp(moving, (float)d + vd.z, (float)h + vh.z, (float)(w + 2) + vw.z);
    out.w = trilerp(moving, (float)d + vd.w, (float)h + vh.w, (float)(w + 3) + vw.w);
    warped4[i4] = out;
}

// ---------------------------------------------------------------------------
// Demon forces (dual) + u = vf + f, then W-axis 7-tap smooth via warp shuffle.
// Lane l holds w = [4l, 4l+3]; a warp spans a full 128-wide row.
// ---------------------------------------------------------------------------
__device__ __forceinline__ float4 grad_s(const float4* __restrict__ a4,
                                         int i4, int c, int s4) {
    float4 p, m;
    if (c == 0) {
        p = a4[i4 + s4]; m = a4[i4];
        return make_float4(p.x - m.x, p.y - m.y, p.z - m.z, p.w - m.w);
    }
    if (c == 127) {
        p = a4[i4]; m = a4[i4 - s4];
        return make_float4(p.x - m.x, p.y - m.y, p.z - m.z, p.w - m.w);
    }
    p = a4[i4 + s4]; m = a4[i4 - s4];
    return make_float4(0.5f * (p.x - m.x), 0.5f * (p.y - m.y),
                       0.5f * (p.z - m.z), 0.5f * (p.w - m.w));
}

__device__ __forceinline__ float4 grad_w_shfl(float4 c, int lane) {
    float lw = __shfl_up_sync(0xFFFFFFFFu, c.w, 1);    // value at w0-1
    float rx = __shfl_down_sync(0xFFFFFFFFu, c.x, 1);  // value at w0+4
    float4 g;
    g.x = (lane == 0)  ? (c.y - c.x) : 0.5f * (c.y - lw);
    g.y = 0.5f * (c.z - c.x);
    g.z = 0.5f * (c.w - c.y);
    g.w = (lane == 31) ? (c.w - c.z) : 0.5f * (rx - c.z);
    return g;
}

__device__ __forceinline__ float4 wsmooth_shfl(float4 u, int lane) {
    float ly = __shfl_up_sync(0xFFFFFFFFu, u.y, 1);
    float lz = __shfl_up_sync(0xFFFFFFFFu, u.z, 1);
    float lw = __shfl_up_sync(0xFFFFFFFFu, u.w, 1);
    float rx = __shfl_down_sync(0xFFFFFFFFu, u.x, 1);
    float ry = __shfl_down_sync(0xFFFFFFFFu, u.y, 1);
    float rz = __shfl_down_sync(0xFFFFFFFFu, u.z, 1);
    if (lane == 0)  { ly = 0.f; lz = 0.f; lw = 0.f; }
    if (lane == 31) { rx = 0.f; ry = 0.f; rz = 0.f; }
    float a[10] = {ly, lz, lw, u.x, u.y, u.z, u.w, rx, ry, rz};
    float4 o;
#pragma unroll
    for (int j = 0; j < 4; j++) {
        float acc = GW[0] * a[3 + j];
#pragma unroll
        for (int t = 1; t <= 3; t++)
            acc += GW[t] * (a[3 + j - t] + a[3 + j + t]);
        ((float*)&o)[j] = acc;
    }
    return o;
}

__global__ void force_w_kernel(const float4* __restrict__ warped4,
                               const float4* __restrict__ fixed4,
                               const uint2* __restrict__ vfh,
                               uint2* __restrict__ uh) {
    int i4 = blockIdx.x * blockDim.x + threadIdx.x;   // over N3/4
    if (i4 >= N3 / 4) return;
    int i = i4 * 4;
    int h = (i >> 7) & 127;
    int d = i >> 14;
    int lane = threadIdx.x & 31;   // == w4 index within the row

    float4 wc = warped4[i4];
    float4 fc = fixed4[i4];

    float4 gdw = grad_s(warped4, i4, d, N2 / 4);
    float4 gdf = grad_s(fixed4,  i4, d, N2 / 4);
    float4 ghw = grad_s(warped4, i4, h, N / 4);
    float4 ghf = grad_s(fixed4,  i4, h, N / 4);
    float4 gww = grad_w_shfl(wc, lane);
    float4 gwf = grad_w_shfl(fc, lane);

    float4 v0 = ld_h4(vfh, i4);
    float4 v1 = ld_h4(vfh, i4 + N3 / 4);
    float4 v2 = ld_h4(vfh, i4 + 2 * N3 / 4);

    float4 u0, u1, u2;
#pragma unroll
    for (int j = 0; j < 4; j++) {
        float diff = ((const float*)&wc)[j] - ((const float*)&fc)[j];
        float g0 = 0.5f * (((const float*)&gdw)[j] + ((const float*)&gdf)[j]);
        float g1 = 0.5f * (((const float*)&ghw)[j] + ((const float*)&ghf)[j]);
        float g2 = 0.5f * (((const float*)&gww)[j] + ((const float*)&gwf)[j]);
        float denom = g0 * g0 + g1 * g1 + g2 * g2 + diff * diff;
        float s = (denom > 1e-6f) ? (diff / denom) : 0.0f;
        ((float*)&u0)[j] = ((const float*)&v0)[j] + s * g0;
        ((float*)&u1)[j] = ((const float*)&v1)[j] + s * g1;
        ((float*)&u2)[j] = ((const float*)&v2)[j] + s * g2;
    }

    // Fused W-axis smoothing (separable passes commute)
    st_h4(uh, i4,              wsmooth_shfl(u0, lane));
    st_h4(uh, i4 + N3 / 4,     wsmooth_shfl(u1, lane));
    st_h4(uh, i4 + 2 * N3 / 4, wsmooth_shfl(u2, lane));
}

// ---------------------------------------------------------------------------
// Strided-axis 7-tap Gaussian, 4 outputs per thread along the axis, fp16 I/O.
// Layout (uint2 granularity = 4 voxels): [outer][axis=128][INNER].
// D axis: INNER = N2/4. H axis: INNER = N/4.
// ---------------------------------------------------------------------------
template <int INNER>
__global__ void smooth_s4_h_kernel(const uint2* __restrict__ in,
                                   uint2* __restrict__ out) {
    int t = blockIdx.x * blockDim.x + threadIdx.x;    // over 3*N3/16
    if (t >= 3 * N3 / 16) return;
    int inner = t % INNER;
    int cb    = (t / INNER) & 31;
    int outer = t / (INNER * 32);
    int c0 = cb * 4;

    const uint2* p = in + (size_t)outer * (128 * INNER) + inner;

    float4 tap[10];
#pragma unroll
    for (int j = 0; j < 10; j++) {
        int c = c0 + j - 3;
        if (c >= 0 && c < 128) tap[j] = ld_h4(p, c * INNER);
        else                   tap[j] = make_float4(0.f, 0.f, 0.f, 0.f);
    }

    uint2* q = out + (size_t)outer * (128 * INNER) + inner;
#pragma unroll
    for (int j = 0; j < 4; j++) {
        float4 acc;
        acc.x = GW[0] * tap[3 + j].x;
        acc.y = GW[0] * tap[3 + j].y;
        acc.z = GW[0] * tap[3 + j].z;
        acc.w = GW[0] * tap[3 + j].w;
#pragma unroll
        for (int s = 1; s <= 3; s++) {
            float4 a = tap[3 + j - s], b = tap[3 + j + s];
            acc.x += GW[s] * (a.x + b.x);
            acc.y += GW[s] * (a.y + b.y);
            acc.z += GW[s] * (a.z + b.z);
            acc.w += GW[s] * (a.w + b.w);
        }
        st_h4(q, (c0 + j) * INNER, acc);
    }
}

// H-axis variant writing fp32 to d_out (final iteration). Same layout, INNER=N/4.
__global__ void smooth_s4_out_kernel(const uint2* __restrict__ in,
                                     float4* __restrict__ out4) {
    const int INNER = N / 4;
    int t = blockIdx.x * blockDim.x + threadIdx.x;    // over 3*N3/16
    if (t >= 3 * N3 / 16) return;
    int inner = t % INNER;
    int cb    = (t / INNER) & 31;
    int outer = t / (INNER * 32);
    int c0 = cb * 4;

    const uint2* p = in + (size_t)outer * (128 * INNER) + inner;

    float4 tap[10];
#pragma unroll
    for (int j = 0; j < 10; j++) {
        int c = c0 + j - 3;
        if (c >= 0 && c < 128) tap[j] = ld_h4(p, c * INNER);
        else                   tap[j] = make_float4(0.f, 0.f, 0.f, 0.f);
    }

    float4* q = out4 + (size_t)outer * (128 * INNER) + inner;
#pragma unroll
    for (int j = 0; j < 4; j++) {
        float4 acc;
        acc.x = GW[0] * tap[3 + j].x;
        acc.y = GW[0] * tap[3 + j].y;
        acc.z = GW[0] * tap[3 + j].z;
        acc.w = GW[0] * tap[3 + j].w;
#pragma unroll
        for (int s = 1; s <= 3; s++) {
            float4 a = tap[3 + j - s], b = tap[3 + j + s];
            acc.x += GW[s] * (a.x + b.x);
            acc.y += GW[s] * (a.y + b.y);
            acc.z += GW[s] * (a.z + b.z);
            acc.w += GW[s] * (a.w + b.w);
        }
        q[(c0 + j) * INNER] = acc;
    }
}

extern "C" void kernel_launch(void* const* d_in, const int* in_sizes, int n_in,
                              void* d_out, int out_size) {
    const float* moving = (const float*)d_in[0];
    const float4* fixed4 = (const float4*)d_in[1];
    float4* vf_out = (float4*)d_out;

    float *warped_p; __half *vfh_p, *uh_p, *th_p;
    cudaGetSymbolAddress((void**)&warped_p, g_warped);
    cudaGetSymbolAddress((void**)&vfh_p, g_vfh);
    cudaGetSymbolAddress((void**)&uh_p, g_uh);
    cudaGetSymbolAddress((void**)&th_p, g_th);
    float4* warped4 = (float4*)warped_p;
    uint2* vfh = (uint2*)vfh_p;
    uint2* uh  = (uint2*)uh_p;
    uint2* th  = (uint2*)th_p;

    const int T = 256;
    const int B1 = (N3 / 4) / T;            // 2048
    const int BZ8 = (3 * N3 / 8) / T;       // 3072
    const int BS = (3 * N3 / 16) / T;       // 1536

    zero_h_kernel<<<BZ8, T>>>((uint4*)vfh);

    for (int it = 0; it < 20; it++) {
        warp_kernel<<<B1, T>>>(moving, vfh, warped4);
        force_w_kernel<<<B1, T>>>(warped4, fixed4, vfh, uh);    // force + W smooth
        smooth_s4_h_kernel<N2 / 4><<<BS, T>>>(uh, th);          // D axis
        if (it < 19)
            smooth_s4_h_kernel<N / 4><<<BS, T>>>(th, vfh);      // H axis -> fp16 vf
        else
            smooth_s4_out_kernel<<<BS, T>>>(th, vf_out);        // final: fp32 d_out
    }
}